// round 5
// baseline (speedup 1.0000x reference)
#include <cuda_runtime.h>
#include <cuda_bf16.h>
#include <math.h>
#include <stdint.h>

#define CDIV(a,b) (((a)+(b)-1)/(b))

__device__ __forceinline__ float gelu_f(float x){
  const float c0 = 0.7978845608028654f;
  return 0.5f*x*(1.f + tanhf(c0*(x + 0.044715f*x*x*x)));
}
__device__ __forceinline__ void mma16816(float* d, const uint32_t* a, const uint32_t* b){
  asm volatile(
    "mma.sync.aligned.m16n8k16.row.col.f32.bf16.bf16.f32 "
    "{%0,%1,%2,%3}, {%4,%5,%6,%7}, {%8,%9}, {%0,%1,%2,%3};"
    : "+f"(d[0]), "+f"(d[1]), "+f"(d[2]), "+f"(d[3])
    : "r"(a[0]), "r"(a[1]), "r"(a[2]), "r"(a[3]), "r"(b[0]), "r"(b[1]));
}
__device__ __forceinline__ void ldm4(uint32_t* r, uint32_t addr){
  asm volatile("ldmatrix.sync.aligned.m8n8.x4.shared.b16 {%0,%1,%2,%3}, [%4];"
    : "=r"(r[0]), "=r"(r[1]), "=r"(r[2]), "=r"(r[3]) : "r"(addr));
}
__device__ __forceinline__ uint32_t smem_u32(const void* p){
  uint32_t a;
  asm("{ .reg .u64 t; cvta.to.shared.u64 t, %1; cvt.u32.u64 %0, t; }" : "=r"(a) : "l"(p));
  return a;
}
__device__ __forceinline__ void cp16(uint32_t dst, const void* src, int sz){
  asm volatile("cp.async.cg.shared.global [%0], [%1], 16, %2;"
               :: "r"(dst), "l"(src), "r"(sz) : "memory");
}
__device__ __forceinline__ void split_bf(float v, __nv_bfloat16& h, __nv_bfloat16& l){
  h = __float2bfloat16_rn(v);
  l = __float2bfloat16_rn(v - __bfloat162float(h));
}

// ================= device scratch =================
__device__ float g_c1[64*8*1800];
__device__ __nv_bfloat16 g_col2h[11520*808], g_col2l[11520*808];
__device__ float g_c2g[11520*80];
__device__ __nv_bfloat16 g_col3h[1152*4080], g_col3l[1152*4080];
__device__ float g_c3[1152*800];
__device__ float g_x[1152*800];
__device__ __nv_bfloat16 g_xh[1152*800], g_xl[1152*800];
__device__ float g_qkv[1152*2400];
__device__ __nv_bfloat16 g_atth[1152*800], g_attl[1152*800];
__device__ float g_t1[1152*800];
__device__ __nv_bfloat16 g_hh[1152*3200], g_hl[1152*3200];
__device__ float g_stats[128];
// weight hi/lo
__device__ __nv_bfloat16 g_w2h[80*808],        g_w2l[80*808];
__device__ __nv_bfloat16 g_w3h[800*4080],      g_w3l[800*4080];
__device__ __nv_bfloat16 g_wiph[8*2400*800],   g_wipl[8*2400*800];
__device__ __nv_bfloat16 g_waoh[8*800*800],    g_waol[8*800*800];
__device__ __nv_bfloat16 g_wl1h[8*3200*800],   g_wl1l[8*3200*800];
__device__ __nv_bfloat16 g_wl2h[8*800*3200],   g_wl2l[8*800*3200];
__device__ __nv_bfloat16 g_wouth[800*800],     g_woutl[800*800];

// ================= weight fp32 -> bf16 hi/lo =================
__global__ void wconv_kernel(const float* __restrict__ w,
    __nv_bfloat16* __restrict__ hi, __nv_bfloat16* __restrict__ lo, int n4)
{
  int i = blockIdx.x*256 + threadIdx.x;
  if (i >= n4) return;
  float4 v = ((const float4*)w)[i];
  __nv_bfloat16 h0,h1,h2,h3,l0,l1,l2,l3;
  split_bf(v.x,h0,l0); split_bf(v.y,h1,l1); split_bf(v.z,h2,l2); split_bf(v.w,h3,l3);
  __nv_bfloat162 ph0 = __nv_bfloat162(h0,h1), ph1 = __nv_bfloat162(h2,h3);
  __nv_bfloat162 pl0 = __nv_bfloat162(l0,l1), pl1 = __nv_bfloat162(l2,l3);
  ((uint2*)hi)[i] = make_uint2(*(uint32_t*)&ph0, *(uint32_t*)&ph1);
  ((uint2*)lo)[i] = make_uint2(*(uint32_t*)&pl0, *(uint32_t*)&pl1);
}

// ======== GEMM v3: C[M,N] = A[M,K] @ B[N,K]^T + bias ========
// Pre-split bf16 hi/lo operands. BM=64, BN=128, BK=32, 256 thr, 8 warps (2x4),
// 3-stage cp.async pipeline, ldmatrix fragment loads.
// 3-term: AhBh + AhBl + AlBh. M%64==0, K%8==0.
#define PADK 40
#define STAGE_ELEM (64*PADK*2 + 128*PADK*2)       // 15360 bf16
#define STAGE_BYTES (STAGE_ELEM*2)                 // 30720
#define GEMM3_SMEM (3*STAGE_BYTES)                 // 92160

template<int ACT, int OUTBF>
__global__ void __launch_bounds__(256) gemm3(
    const __nv_bfloat16* __restrict__ Ah, const __nv_bfloat16* __restrict__ Al,
    const __nv_bfloat16* __restrict__ Bh, const __nv_bfloat16* __restrict__ Bl,
    const float* __restrict__ bias, float* __restrict__ C,
    __nv_bfloat16* __restrict__ Ch, __nv_bfloat16* __restrict__ Cl,
    int M, int N, int K)
{
  extern __shared__ __align__(16) __nv_bfloat16 sm[];
  const int tid = threadIdx.x;
  const int wid = tid >> 5;
  const int lane = tid & 31;
  const int g = lane >> 2;
  const int t2 = (lane & 3) * 2;
  const int wm = wid >> 2;
  const int wn = wid & 3;
  const int bm = blockIdx.y * 64;
  const int bn = blockIdx.x * 128;
  const uint32_t smb = smem_u32(sm);

  // ldmatrix per-lane addresses (byte offsets within a stage)
  const int j8 = lane >> 3, lr = lane & 7;
  const uint32_t offA0 = (uint32_t)((wm*32 + 0*16 + (j8&1)*8 + lr)*PADK + (j8>>1)*8)*2;
  const uint32_t offA1 = (uint32_t)((wm*32 + 1*16 + (j8&1)*8 + lr)*PADK + (j8>>1)*8)*2;
  const uint32_t offB0 = (uint32_t)((wn*32 + 0*16 + (j8>>1)*8 + lr)*PADK + (j8&1)*8)*2;
  const uint32_t offB1 = (uint32_t)((wn*32 + 1*16 + (j8>>1)*8 + lr)*PADK + (j8&1)*8)*2;
  const uint32_t ALOFF = 64u*PADK*2;
  const uint32_t BHOFF = 128u*PADK*2;
  const uint32_t BLOFF = BHOFF + 128u*PADK*2;

  float acc[2][4][4];
  #pragma unroll
  for (int i=0;i<2;++i)
    #pragma unroll
    for (int jj=0;jj<4;++jj)
      #pragma unroll
      for (int k=0;k<4;++k) acc[i][jj][k]=0.f;

  const int nstage = CDIV(K, 32);

  auto load_stage = [&](int s){
    const uint32_t base = smb + (uint32_t)(s % 3) * STAGE_BYTES;
    const int k0 = s * 32;
    {
      int r = tid >> 2, c = (tid & 3) * 8;
      uint32_t d = base + (uint32_t)(r*PADK + c)*2;
      int gk = k0 + c;
      int sz = (gk < K) ? 16 : 0;
      size_t off = (size_t)(bm + r)*K + gk;
      cp16(d,         Ah + off, sz);
      cp16(d + ALOFF, Al + off, sz);
    }
    #pragma unroll
    for (int jj = 0; jj < 2; ++jj) {
      int sid = tid + jj*256;
      int r = sid >> 2, c = (sid & 3) * 8;
      uint32_t d = base + BHOFF + (uint32_t)(r*PADK + c)*2;
      int gk = k0 + c;
      int rb = bn + r;
      int sz = (rb < N && gk < K) ? 16 : 0;
      size_t off = (size_t)(sz ? rb : 0)*K + (sz ? gk : 0);
      cp16(d,                   Bh + off, sz);
      cp16(d + (BLOFF - BHOFF), Bl + off, sz);
    }
    asm volatile("cp.async.commit_group;" ::: "memory");
  };

  load_stage(0);
  if (nstage > 1) load_stage(1);

  for (int s = 0; s < nstage; ++s) {
    if (s + 2 < nstage) {
      load_stage(s + 2);
      asm volatile("cp.async.wait_group 2;" ::: "memory");
    } else if (s + 1 < nstage) {
      asm volatile("cp.async.wait_group 1;" ::: "memory");
    } else {
      asm volatile("cp.async.wait_group 0;" ::: "memory");
    }
    __syncthreads();

    const uint32_t stA = smb + (uint32_t)(s % 3) * STAGE_BYTES;
    const uint32_t stB = stA + BHOFF;

    #pragma unroll
    for (int ks = 0; ks < 32; ks += 16) {
      const uint32_t kd = (uint32_t)ks * 2;
      uint32_t ah0[4], ah1[4], al0[4], al1[4], bq0[4], bq1[4], lq0[4], lq1[4];
      ldm4(ah0, stA + offA0 + kd);
      ldm4(ah1, stA + offA1 + kd);
      ldm4(al0, stA + ALOFF + offA0 + kd);
      ldm4(al1, stA + ALOFF + offA1 + kd);
      ldm4(bq0, stB + offB0 + kd);
      ldm4(bq1, stB + offB1 + kd);
      ldm4(lq0, stB + (BLOFF - BHOFF) + offB0 + kd);
      ldm4(lq1, stB + (BLOFF - BHOFF) + offB1 + kd);

      const uint32_t* bh[4] = { &bq0[0], &bq0[2], &bq1[0], &bq1[2] };
      const uint32_t* bl[4] = { &lq0[0], &lq0[2], &lq1[0], &lq1[2] };
      uint32_t* ah[2] = { ah0, ah1 };
      uint32_t* al[2] = { al0, al1 };

      #pragma unroll
      for (int mf = 0; mf < 2; ++mf)
        #pragma unroll
        for (int nf = 0; nf < 4; ++nf) {
          mma16816(acc[mf][nf], ah[mf], bh[nf]);
          mma16816(acc[mf][nf], ah[mf], bl[nf]);
          mma16816(acc[mf][nf], al[mf], bh[nf]);
        }
    }
    __syncthreads();
  }

  // ---- epilogue ----
  #pragma unroll
  for (int mf = 0; mf < 2; ++mf) {
    int row0 = bm + wm*32 + mf*16 + g;
    #pragma unroll
    for (int nf = 0; nf < 4; ++nf) {
      int col = bn + wn*32 + nf*8 + t2;
      if (col >= N) continue;
      float b0 = bias[col];
      float b1 = (col+1 < N) ? bias[col+1] : 0.f;
      float v0 = acc[mf][nf][0] + b0, v1 = acc[mf][nf][1] + b1;
      float v2 = acc[mf][nf][2] + b0, v3 = acc[mf][nf][3] + b1;
      if (ACT == 1) { v0=gelu_f(v0); v1=gelu_f(v1); v2=gelu_f(v2); v3=gelu_f(v3); }
      if (OUTBF == 0) {
        if (col+1 < N) {
          *(float2*)(C + (size_t)row0*N + col)     = make_float2(v0, v1);
          *(float2*)(C + (size_t)(row0+8)*N + col) = make_float2(v2, v3);
        } else {
          C[(size_t)row0*N + col] = v0;
          C[(size_t)(row0+8)*N + col] = v2;
        }
      } else {
        __nv_bfloat16 h,l;
        split_bf(v0,h,l); Ch[(size_t)row0*N+col]=h;     Cl[(size_t)row0*N+col]=l;
        split_bf(v2,h,l); Ch[(size_t)(row0+8)*N+col]=h; Cl[(size_t)(row0+8)*N+col]=l;
        if (col+1 < N) {
          split_bf(v1,h,l); Ch[(size_t)row0*N+col+1]=h;     Cl[(size_t)row0*N+col+1]=l;
          split_bf(v3,h,l); Ch[(size_t)(row0+8)*N+col+1]=h; Cl[(size_t)(row0+8)*N+col+1]=l;
        }
      }
    }
  }
}

// ================= conv1 =================
__global__ __launch_bounds__(128) void conv1_kernel(const float* __restrict__ src,
    const float* __restrict__ w, const float* __restrict__ bias, float* __restrict__ out)
{
  const int b  = blockIdx.x;
  const int l0 = blockIdx.y * 128;
  const int t  = threadIdx.x;
  __shared__ float s_in[836];
  __shared__ float s_w[8*201];
  float acc[8];
  #pragma unroll
  for (int o=0;o<8;++o) acc[o]=0.f;
  const int base = 5*l0 - 100;
  for (int i = 0; i < 12; ++i) {
    for (int j = t; j < 836; j += 128) {
      int p = base + j;
      s_in[j] = (p >= 0 && p < 9000) ? src[(size_t)(b*12+i)*9000 + p] : 0.f;
    }
    for (int j = t; j < 8*201; j += 128) {
      int o = j / 201, k = j % 201;
      s_w[j] = w[(size_t)(o*12 + i)*201 + k];
    }
    __syncthreads();
    if (l0 + t < 1800) {
      for (int k = 0; k < 201; ++k) {
        float v = s_in[5*t + k];
        #pragma unroll
        for (int o = 0; o < 8; ++o) acc[o] = fmaf(v, s_w[o*201 + k], acc[o]);
      }
    }
    __syncthreads();
  }
  int l = l0 + t;
  if (l < 1800) {
    #pragma unroll
    for (int o = 0; o < 8; ++o)
      out[(size_t)(b*8+o)*1800 + l] = acc[o] + bias[o];
  }
}

// ================= GroupNorm(1) stats =================
__global__ __launch_bounds__(256) void gn_stats_kernel(const float* __restrict__ x,
                                                       float* __restrict__ stats, int n)
{
  const int b = blockIdx.x;
  const float* xb = x + (size_t)b * n;
  float s = 0.f, q = 0.f;
  for (int i = threadIdx.x; i < n; i += 256) { float v = xb[i]; s += v; q += v*v; }
  __shared__ float sh1[256], sh2[256];
  sh1[threadIdx.x] = s; sh2[threadIdx.x] = q;
  __syncthreads();
  for (int st = 128; st > 0; st >>= 1) {
    if (threadIdx.x < st) { sh1[threadIdx.x] += sh1[threadIdx.x+st]; sh2[threadIdx.x] += sh2[threadIdx.x+st]; }
    __syncthreads();
  }
  if (threadIdx.x == 0) {
    float m = sh1[0] / n;
    float v = sh2[0] / n - m*m;
    stats[2*b]   = m;
    stats[2*b+1] = rsqrtf(v + 1e-5f);
  }
}

// ============ im2col conv2 + GN1 + GELU -> bf16 hi/lo ============
__global__ void im2col2_kernel(const float* __restrict__ c1,
    __nv_bfloat16* __restrict__ colh, __nv_bfloat16* __restrict__ coll,
    const float* __restrict__ stats, const float* __restrict__ g, const float* __restrict__ be)
{
  int idx = blockIdx.x*blockDim.x + threadIdx.x;
  if (idx >= 11520*808) return;
  int row = idx / 808, c = idx % 808;
  int i = c / 101, kk = c % 101;
  int b = row / 180, l = row % 180;
  int p = 10*l + kk - 50;
  float v = 0.f;
  if (p >= 0 && p < 1800) {
    float m = stats[2*b], r = stats[2*b+1];
    v = gelu_f((c1[(size_t)(b*8+i)*1800 + p] - m)*r*g[i] + be[i]);
  }
  __nv_bfloat16 h,l2; split_bf(v,h,l2);
  colh[idx]=h; coll[idx]=l2;
}

// ============ im2col conv3 + GN2 + GELU -> bf16 hi/lo ============
__global__ void im2col3_kernel(const float* __restrict__ c2g,
    __nv_bfloat16* __restrict__ colh, __nv_bfloat16* __restrict__ coll,
    const float* __restrict__ stats, const float* __restrict__ g, const float* __restrict__ be)
{
  int idx = blockIdx.x*blockDim.x + threadIdx.x;
  if (idx >= 1152*4080) return;
  int row = idx / 4080, c = idx % 4080;
  int i = c / 51, k = c % 51;
  int b = row / 18, l = row % 18;
  int p = 10*l + k - 25;
  float v = 0.f;
  if (p >= 0 && p < 180) {
    float m = stats[2*b], r = stats[2*b+1];
    v = gelu_f((c2g[(size_t)(b*180+p)*80 + i] - m)*r*g[i] + be[i]);
  }
  __nv_bfloat16 h,l2; split_bf(v,h,l2);
  colh[idx]=h; coll[idx]=l2;
}

// GN3 + GELU + PE -> x fp32 and bf16 hi/lo
__global__ void gn3_pe_kernel(const float* __restrict__ x, float* __restrict__ y,
    __nv_bfloat16* __restrict__ yh, __nv_bfloat16* __restrict__ yl,
    const float* __restrict__ stats, const float* __restrict__ g, const float* __restrict__ be)
{
  int idx = blockIdx.x*blockDim.x + threadIdx.x;
  if (idx >= 1152*800) return;
  int row = idx / 800, d = idx % 800;
  int b = row / 18, s = row % 18;
  float m = stats[2*b], r = stats[2*b+1];
  float v = gelu_f((x[idx]-m)*r*g[d] + be[d]);
  int de = d & ~1;
  float freq = expf((float)de * (-9.210340371976184f/800.f));
  float ang = (float)s * freq;
  v += (d & 1) ? cosf(ang) : sinf(ang);
  y[idx] = v;
  __nv_bfloat16 h,l; split_bf(v,h,l);
  yh[idx]=h; yl[idx]=l;
}

// ================= attention -> bf16 hi/lo out =================
__global__ __launch_bounds__(128) void attn_kernel(const float* __restrict__ qkv,
    __nv_bfloat16* __restrict__ outh, __nv_bfloat16* __restrict__ outl)
{
  const int b = blockIdx.x, h = blockIdx.y;
  const int tid = threadIdx.x;
  __shared__ float sq[1800], sk[1800], sv[1800], sc[324];
  for (int idx = tid; idx < 1800; idx += 128) {
    int s = idx/100, d = idx%100;
    size_t base = (size_t)(b*18+s)*2400 + h*100 + d;
    sq[idx] = qkv[base];
    sk[idx] = qkv[base + 800];
    sv[idx] = qkv[base + 1600];
  }
  __syncthreads();
  for (int p = tid; p < 324; p += 128) {
    int i = p/18, j = p%18;
    float dot = 0.f;
    #pragma unroll 4
    for (int d = 0; d < 100; ++d) dot = fmaf(sq[i*100+d], sk[j*100+d], dot);
    int di = i - j; if (di < 0) di = -di;
    float bias = (di > 2 && i != 0 && j != 0) ? -1e30f : 0.f;
    sc[p] = dot * 0.1f + bias;
  }
  __syncthreads();
  if (tid < 18) {
    float mx = -1e30f;
    for (int j = 0; j < 18; ++j) mx = fmaxf(mx, sc[tid*18+j]);
    float sum = 0.f;
    for (int j = 0; j < 18; ++j) { float e = expf(sc[tid*18+j]-mx); sc[tid*18+j] = e; sum += e; }
    float inv = 1.f/sum;
    for (int j = 0; j < 18; ++j) sc[tid*18+j] *= inv;
  }
  __syncthreads();
  for (int idx = tid; idx < 1800; idx += 128) {
    int i = idx/100, d = idx%100;
    float o = 0.f;
    #pragma unroll
    for (int j = 0; j < 18; ++j) o = fmaf(sc[i*18+j], sv[j*100+d], o);
    size_t oi = (size_t)(b*18+i)*800 + h*100 + d;
    __nv_bfloat16 hh,ll; split_bf(o,hh,ll);
    outh[oi]=hh; outl[oi]=ll;
  }
}

// ================= residual add + LayerNorm -> x fp32 + bf16 hi/lo =================
__global__ __launch_bounds__(256) void add_ln_kernel(float* __restrict__ x,
    __nv_bfloat16* __restrict__ xh, __nv_bfloat16* __restrict__ xl,
    const float* __restrict__ a, const float* __restrict__ g, const float* __restrict__ be)
{
  const int row = blockIdx.x;
  const int tid = threadIdx.x;
  __shared__ float t[800];
  __shared__ float sh1[256], sh2[256];
  float s = 0.f, q = 0.f;
  for (int d = tid; d < 800; d += 256) {
    float v = x[(size_t)row*800 + d] + a[(size_t)row*800 + d];
    t[d] = v; s += v; q += v*v;
  }
  sh1[tid] = s; sh2[tid] = q;
  __syncthreads();
  for (int st = 128; st > 0; st >>= 1) {
    if (tid < st) { sh1[tid] += sh1[tid+st]; sh2[tid] += sh2[tid+st]; }
    __syncthreads();
  }
  float m = sh1[0] / 800.f;
  float r = rsqrtf(sh2[0] / 800.f - m*m + 1e-5f);
  for (int d = tid; d < 800; d += 256) {
    float v = (t[d]-m)*r*g[d] + be[d];
    x[(size_t)row*800 + d] = v;
    __nv_bfloat16 h,l; split_bf(v,h,l);
    xh[(size_t)row*800 + d]=h; xl[(size_t)row*800 + d]=l;
  }
}

// ================= host =================
static float* symf(const void* s){ void* p; cudaGetSymbolAddress(&p, s); return (float*)p; }
static __nv_bfloat16* symb(const void* s){ void* p; cudaGetSymbolAddress(&p, s); return (__nv_bfloat16*)p; }

extern "C" void kernel_launch(void* const* d_in, const int* in_sizes, int n_in,
                              void* d_out, int out_size)
{
  const float* src        = (const float*)d_in[0];
  const float* cw1        = (const float*)d_in[1];
  const float* cb1        = (const float*)d_in[2];
  const float* gn1_g      = (const float*)d_in[3];
  const float* gn1_b      = (const float*)d_in[4];
  const float* cw2        = (const float*)d_in[5];
  const float* cb2        = (const float*)d_in[6];
  const float* gn2_g      = (const float*)d_in[7];
  const float* gn2_b      = (const float*)d_in[8];
  const float* cw3        = (const float*)d_in[9];
  const float* cb3        = (const float*)d_in[10];
  const float* gn3_g      = (const float*)d_in[11];
  const float* gn3_b      = (const float*)d_in[12];
  const float* in_proj_w  = (const float*)d_in[13];
  const float* in_proj_b  = (const float*)d_in[14];
  const float* attn_out_w = (const float*)d_in[15];
  const float* attn_out_b = (const float*)d_in[16];
  const float* lin1_w     = (const float*)d_in[17];
  const float* lin1_b     = (const float*)d_in[18];
  const float* lin2_w     = (const float*)d_in[19];
  const float* lin2_b     = (const float*)d_in[20];
  const float* ln1_g      = (const float*)d_in[21];
  const float* ln1_b      = (const float*)d_in[22];
  const float* ln2_g      = (const float*)d_in[23];
  const float* ln2_b      = (const float*)d_in[24];
  const float* out_w      = (const float*)d_in[25];
  const float* out_b      = (const float*)d_in[26];

  float* c1   = symf(g_c1);
  float* c2g  = symf(g_c2g);
  float* c3   = symf(g_c3);
  float* x    = symf(g_x);
  float* qkv  = symf(g_qkv);
  float* t1   = symf(g_t1);
  float* st   = symf(g_stats);
  __nv_bfloat16 *col2h=symb(g_col2h), *col2l=symb(g_col2l);
  __nv_bfloat16 *col3h=symb(g_col3h), *col3l=symb(g_col3l);
  __nv_bfloat16 *xh=symb(g_xh), *xl=symb(g_xl);
  __nv_bfloat16 *atth=symb(g_atth), *attl=symb(g_attl);
  __nv_bfloat16 *hh=symb(g_hh), *hl=symb(g_hl);
  __nv_bfloat16 *w2h=symb(g_w2h), *w2l=symb(g_w2l);
  __nv_bfloat16 *w3h=symb(g_w3h), *w3l=symb(g_w3l);
  __nv_bfloat16 *wiph=symb(g_wiph), *wipl=symb(g_wipl);
  __nv_bfloat16 *waoh=symb(g_waoh), *waol=symb(g_waol);
  __nv_bfloat16 *wl1h=symb(g_wl1h), *wl1l=symb(g_wl1l);
  __nv_bfloat16 *wl2h=symb(g_wl2h), *wl2l=symb(g_wl2l);
  __nv_bfloat16 *wouth=symb(g_wouth), *woutl=symb(g_woutl);

  cudaFuncSetAttribute(gemm3<0,0>, cudaFuncAttributeMaxDynamicSharedMemorySize, GEMM3_SMEM);
  cudaFuncSetAttribute(gemm3<1,1>, cudaFuncAttributeMaxDynamicSharedMemorySize, GEMM3_SMEM);

  // ---- weight conversions ----
  wconv_kernel<<<CDIV(80*808/4,256),256>>>(cw2, w2h, w2l, 80*808/4);
  wconv_kernel<<<CDIV(800*4080/4,256),256>>>(cw3, w3h, w3l, 800*4080/4);
  wconv_kernel<<<CDIV(8*2400*800/4,256),256>>>(in_proj_w, wiph, wipl, 8*2400*800/4);
  wconv_kernel<<<CDIV(8*800*800/4,256),256>>>(attn_out_w, waoh, waol, 8*800*800/4);
  wconv_kernel<<<CDIV(8*3200*800/4,256),256>>>(lin1_w, wl1h, wl1l, 8*3200*800/4);
  wconv_kernel<<<CDIV(8*800*3200/4,256),256>>>(lin2_w, wl2h, wl2l, 8*800*3200/4);
  wconv_kernel<<<CDIV(800*800/4,256),256>>>(out_w, wouth, woutl, 800*800/4);

  // ---- patch embedding ----
  conv1_kernel<<<dim3(64,15),128>>>(src, cw1, cb1, c1);
  gn_stats_kernel<<<64,256>>>(c1, st, 8*1800);
  im2col2_kernel<<<CDIV(11520*808,256),256>>>(c1, col2h, col2l, st, gn1_g, gn1_b);
  gemm3<0,0><<<dim3(1,180),256,GEMM3_SMEM>>>(col2h, col2l, w2h, w2l, cb2, c2g,
                                             nullptr, nullptr, 11520, 80, 808);
  gn_stats_kernel<<<64,256>>>(c2g, st, 180*80);
  im2col3_kernel<<<CDIV(1152*4080,256),256>>>(c2g, col3h, col3l, st, gn2_g, gn2_b);
  gemm3<0,0><<<dim3(7,18),256,GEMM3_SMEM>>>(col3h, col3l, w3h, w3l, cb3, c3,
                                            nullptr, nullptr, 1152, 800, 4080);
  gn_stats_kernel<<<64,256>>>(c3, st, 18*800);
  gn3_pe_kernel<<<CDIV(1152*800,256),256>>>(c3, x, xh, xl, st, gn3_g, gn3_b);

  // ---- transformer layers ----
  for (int i = 0; i < 8; ++i) {
    gemm3<0,0><<<dim3(19,18),256,GEMM3_SMEM>>>(xh, xl,
        wiph + (size_t)i*2400*800, wipl + (size_t)i*2400*800,
        in_proj_b + (size_t)i*2400, qkv, nullptr, nullptr, 1152, 2400, 800);
    attn_kernel<<<dim3(64,8),128>>>(qkv, atth, attl);
    gemm3<0,0><<<dim3(7,18),256,GEMM3_SMEM>>>(atth, attl,
        waoh + (size_t)i*800*800, waol + (size_t)i*800*800,
        attn_out_b + (size_t)i*800, t1, nullptr, nullptr, 1152, 800, 800);
    add_ln_kernel<<<1152,256>>>(x, xh, xl, t1, ln1_g + (size_t)i*800, ln1_b + (size_t)i*800);
    gemm3<1,1><<<dim3(25,18),256,GEMM3_SMEM>>>(xh, xl,
        wl1h + (size_t)i*3200*800, wl1l + (size_t)i*3200*800,
        lin1_b + (size_t)i*3200, nullptr, hh, hl, 1152, 3200, 800);
    gemm3<0,0><<<dim3(7,18),256,GEMM3_SMEM>>>(hh, hl,
        wl2h + (size_t)i*800*3200, wl2l + (size_t)i*800*3200,
        lin2_b + (size_t)i*800, t1, nullptr, nullptr, 1152, 800, 3200);
    add_ln_kernel<<<1152,256>>>(x, xh, xl, t1, ln2_g + (size_t)i*800, ln2_b + (size_t)i*800);
  }

  // ---- output projection ----
  gemm3<0,0><<<dim3(7,18),256,GEMM3_SMEM>>>(xh, xl, wouth, woutl, out_b,
                                            (float*)d_out, nullptr, nullptr, 1152, 800, 800);
}

// round 6
// speedup vs baseline: 1.0472x; 1.0472x over previous
#include <cuda_runtime.h>
#include <cuda_bf16.h>
#include <math.h>
#include <stdint.h>

#define CDIV(a,b) (((a)+(b)-1)/(b))

__device__ __forceinline__ float gelu_f(float x){
  const float c0 = 0.7978845608028654f;
  return 0.5f*x*(1.f + tanhf(c0*(x + 0.044715f*x*x*x)));
}
__device__ __forceinline__ void mma16816(float* d, const uint32_t* a, const uint32_t* b){
  asm volatile(
    "mma.sync.aligned.m16n8k16.row.col.f32.bf16.bf16.f32 "
    "{%0,%1,%2,%3}, {%4,%5,%6,%7}, {%8,%9}, {%0,%1,%2,%3};"
    : "+f"(d[0]), "+f"(d[1]), "+f"(d[2]), "+f"(d[3])
    : "r"(a[0]), "r"(a[1]), "r"(a[2]), "r"(a[3]), "r"(b[0]), "r"(b[1]));
}
__device__ __forceinline__ void ldm4(uint32_t* r, uint32_t addr){
  asm volatile("ldmatrix.sync.aligned.m8n8.x4.shared.b16 {%0,%1,%2,%3}, [%4];"
    : "=r"(r[0]), "=r"(r[1]), "=r"(r[2]), "=r"(r[3]) : "r"(addr));
}
__device__ __forceinline__ uint32_t smem_u32(const void* p){
  uint32_t a;
  asm("{ .reg .u64 t; cvta.to.shared.u64 t, %1; cvt.u32.u64 %0, t; }" : "=r"(a) : "l"(p));
  return a;
}
__device__ __forceinline__ void cp16(uint32_t dst, const void* src, int sz){
  asm volatile("cp.async.cg.shared.global [%0], [%1], 16, %2;"
               :: "r"(dst), "l"(src), "r"(sz) : "memory");
}
__device__ __forceinline__ void split_bf(float v, __nv_bfloat16& h, __nv_bfloat16& l){
  h = __float2bfloat16_rn(v);
  l = __float2bfloat16_rn(v - __bfloat162float(h));
}

// ================= device scratch =================
__device__ float g_c1[64*8*1800];
__device__ __nv_bfloat16 g_col2h[11520*808], g_col2l[11520*808];
__device__ float g_c2g[11520*80];
__device__ __nv_bfloat16 g_col3h[1152*4080], g_col3l[1152*4080];
__device__ float g_c3[1152*800];
__device__ float g_x[1152*800];
__device__ __nv_bfloat16 g_xh[1152*800], g_xl[1152*800];
__device__ float g_qkv[1152*2400];
__device__ __nv_bfloat16 g_atth[1152*800], g_attl[1152*800];
__device__ float g_t1[1152*800];
__device__ __nv_bfloat16 g_hh[1152*3200], g_hl[1152*3200];
__device__ float g_stats[128];
// weight hi/lo
__device__ __nv_bfloat16 g_w2h[80*808],        g_w2l[80*808];
__device__ __nv_bfloat16 g_w3h[800*4080],      g_w3l[800*4080];
__device__ __nv_bfloat16 g_wiph[8*2400*800],   g_wipl[8*2400*800];
__device__ __nv_bfloat16 g_waoh[8*800*800],    g_waol[8*800*800];
__device__ __nv_bfloat16 g_wl1h[8*3200*800],   g_wl1l[8*3200*800];
__device__ __nv_bfloat16 g_wl2h[8*800*3200],   g_wl2l[8*800*3200];
__device__ __nv_bfloat16 g_wouth[800*800],     g_woutl[800*800];

// ================= weight fp32 -> bf16 hi/lo =================
__global__ void wconv_kernel(const float* __restrict__ w,
    __nv_bfloat16* __restrict__ hi, __nv_bfloat16* __restrict__ lo, int n4)
{
  int i = blockIdx.x*256 + threadIdx.x;
  if (i >= n4) return;
  float4 v = ((const float4*)w)[i];
  __nv_bfloat16 h0,h1,h2,h3,l0,l1,l2,l3;
  split_bf(v.x,h0,l0); split_bf(v.y,h1,l1); split_bf(v.z,h2,l2); split_bf(v.w,h3,l3);
  __nv_bfloat162 ph0 = __nv_bfloat162(h0,h1), ph1 = __nv_bfloat162(h2,h3);
  __nv_bfloat162 pl0 = __nv_bfloat162(l0,l1), pl1 = __nv_bfloat162(l2,l3);
  ((uint2*)hi)[i] = make_uint2(*(uint32_t*)&ph0, *(uint32_t*)&ph1);
  ((uint2*)lo)[i] = make_uint2(*(uint32_t*)&pl0, *(uint32_t*)&pl1);
}

// ======== GEMM v4: round-4 two-stage skeleton + ldmatrix fragment loads ========
// C[M,N] = A[M,K] @ B[N,K]^T + bias. Pre-split bf16 hi/lo operands.
// BM=64, BN=128, BK=32, 256 thr, 8 warps (2x4), cp.async double-buffered.
// 3-term: AhBh + AhBl + AlBh. M%64==0, K%8==0.
#define PADK 40
#define STAGE_ELEM (64*PADK*2 + 128*PADK*2)   // 15360 bf16
#define STAGE_BYTES (STAGE_ELEM*2)            // 30720
#define GEMM4_SMEM (2*STAGE_BYTES)            // 61440

template<int ACT, int OUTBF>
__global__ void __launch_bounds__(256) gemm4(
    const __nv_bfloat16* __restrict__ Ah, const __nv_bfloat16* __restrict__ Al,
    const __nv_bfloat16* __restrict__ Bh, const __nv_bfloat16* __restrict__ Bl,
    const float* __restrict__ bias, float* __restrict__ C,
    __nv_bfloat16* __restrict__ Ch, __nv_bfloat16* __restrict__ Cl,
    int M, int N, int K)
{
  extern __shared__ __align__(16) __nv_bfloat16 sm[];
  const int tid = threadIdx.x;
  const int wid = tid >> 5;
  const int lane = tid & 31;
  const int g = lane >> 2;
  const int t2 = (lane & 3) * 2;
  const int wm = wid >> 2;
  const int wn = wid & 3;
  const int bm = blockIdx.y * 64;
  const int bn = blockIdx.x * 128;
  const uint32_t smb = smem_u32(sm);

  // ldmatrix per-lane base offsets (bytes within a stage)
  const int j8 = lane >> 3, lr = lane & 7;
  const uint32_t offA0 = (uint32_t)((wm*32 + 0*16 + (j8&1)*8 + lr)*PADK + (j8>>1)*8)*2;
  const uint32_t offA1 = (uint32_t)((wm*32 + 1*16 + (j8&1)*8 + lr)*PADK + (j8>>1)*8)*2;
  const uint32_t offB0 = (uint32_t)((wn*32 + 0*16 + (j8>>1)*8 + lr)*PADK + (j8&1)*8)*2;
  const uint32_t offB1 = (uint32_t)((wn*32 + 1*16 + (j8>>1)*8 + lr)*PADK + (j8&1)*8)*2;
  const uint32_t ALOFF = 64u*PADK*2;
  const uint32_t BHOFF = 128u*PADK*2;
  const uint32_t BLOFF = 128u*PADK*2;   // relative to B-hi base

  float acc[2][4][4];
  #pragma unroll
  for (int i=0;i<2;++i)
    #pragma unroll
    for (int jj=0;jj<4;++jj)
      #pragma unroll
      for (int k=0;k<4;++k) acc[i][jj][k]=0.f;

  const int nstage = CDIV(K, 32);

  auto load_stage = [&](int s){
    const int buf = s & 1;
    const uint32_t base = smb + (uint32_t)buf * STAGE_BYTES;
    const int k0 = s * 32;
    {
      int r = tid >> 2, c = (tid & 3) * 8;
      uint32_t d = base + (uint32_t)(r*PADK + c)*2;
      int gk = k0 + c;
      int sz = (gk < K) ? 16 : 0;
      size_t off = (size_t)(bm + r)*K + gk;
      cp16(d,         Ah + off, sz);
      cp16(d + ALOFF, Al + off, sz);
    }
    #pragma unroll
    for (int jj = 0; jj < 2; ++jj) {
      int sid = tid + jj*256;
      int r = sid >> 2, c = (sid & 3) * 8;
      uint32_t d = base + BHOFF + (uint32_t)(r*PADK + c)*2;
      int gk = k0 + c;
      int rb = bn + r;
      int sz = (rb < N && gk < K) ? 16 : 0;
      size_t off = (size_t)(sz ? rb : 0)*K + (sz ? gk : 0);
      cp16(d,         Bh + off, sz);
      cp16(d + BLOFF, Bl + off, sz);
    }
    asm volatile("cp.async.commit_group;" ::: "memory");
  };

  load_stage(0);

  for (int s = 0; s < nstage; ++s) {
    if (s + 1 < nstage) {
      load_stage(s + 1);
      asm volatile("cp.async.wait_group 1;" ::: "memory");
    } else {
      asm volatile("cp.async.wait_group 0;" ::: "memory");
    }
    __syncthreads();

    const uint32_t stA = smb + (uint32_t)(s & 1) * STAGE_BYTES;
    const uint32_t stB = stA + BHOFF;

    #pragma unroll
    for (int ks = 0; ks < 32; ks += 16) {
      const uint32_t kd = (uint32_t)ks * 2;
      uint32_t ah0[4], ah1[4], al0[4], al1[4], bq0[4], bq1[4], lq0[4], lq1[4];
      ldm4(ah0, stA + offA0 + kd);
      ldm4(ah1, stA + offA1 + kd);
      ldm4(al0, stA + ALOFF + offA0 + kd);
      ldm4(al1, stA + ALOFF + offA1 + kd);
      ldm4(bq0, stB + offB0 + kd);
      ldm4(bq1, stB + offB1 + kd);
      ldm4(lq0, stB + BLOFF + offB0 + kd);
      ldm4(lq1, stB + BLOFF + offB1 + kd);

      const uint32_t* bh[4] = { &bq0[0], &bq0[2], &bq1[0], &bq1[2] };
      const uint32_t* bl[4] = { &lq0[0], &lq0[2], &lq1[0], &lq1[2] };
      uint32_t* ah[2] = { ah0, ah1 };
      uint32_t* al[2] = { al0, al1 };

      #pragma unroll
      for (int mf = 0; mf < 2; ++mf)
        #pragma unroll
        for (int nf = 0; nf < 4; ++nf) {
          mma16816(acc[mf][nf], ah[mf], bh[nf]);
          mma16816(acc[mf][nf], ah[mf], bl[nf]);
          mma16816(acc[mf][nf], al[mf], bh[nf]);
        }
    }
    __syncthreads();
  }

  // ---- epilogue ----
  #pragma unroll
  for (int mf = 0; mf < 2; ++mf) {
    int row0 = bm + wm*32 + mf*16 + g;
    #pragma unroll
    for (int nf = 0; nf < 4; ++nf) {
      int col = bn + wn*32 + nf*8 + t2;
      if (col >= N) continue;
      float b0 = bias[col];
      float b1 = (col+1 < N) ? bias[col+1] : 0.f;
      float v0 = acc[mf][nf][0] + b0, v1 = acc[mf][nf][1] + b1;
      float v2 = acc[mf][nf][2] + b0, v3 = acc[mf][nf][3] + b1;
      if (ACT == 1) { v0=gelu_f(v0); v1=gelu_f(v1); v2=gelu_f(v2); v3=gelu_f(v3); }
      if (OUTBF == 0) {
        if (col+1 < N) {
          *(float2*)(C + (size_t)row0*N + col)     = make_float2(v0, v1);
          *(float2*)(C + (size_t)(row0+8)*N + col) = make_float2(v2, v3);
        } else {
          C[(size_t)row0*N + col] = v0;
          C[(size_t)(row0+8)*N + col] = v2;
        }
      } else {
        __nv_bfloat16 h,l;
        split_bf(v0,h,l); Ch[(size_t)row0*N+col]=h;     Cl[(size_t)row0*N+col]=l;
        split_bf(v2,h,l); Ch[(size_t)(row0+8)*N+col]=h; Cl[(size_t)(row0+8)*N+col]=l;
        if (col+1 < N) {
          split_bf(v1,h,l); Ch[(size_t)row0*N+col+1]=h;     Cl[(size_t)row0*N+col+1]=l;
          split_bf(v3,h,l); Ch[(size_t)(row0+8)*N+col+1]=h; Cl[(size_t)(row0+8)*N+col+1]=l;
        }
      }
    }
  }
}

// ================= conv1 =================
__global__ __launch_bounds__(128) void conv1_kernel(const float* __restrict__ src,
    const float* __restrict__ w, const float* __restrict__ bias, float* __restrict__ out)
{
  const int b  = blockIdx.x;
  const int l0 = blockIdx.y * 128;
  const int t  = threadIdx.x;
  __shared__ float s_in[836];
  __shared__ float s_w[8*201];
  float acc[8];
  #pragma unroll
  for (int o=0;o<8;++o) acc[o]=0.f;
  const int base = 5*l0 - 100;
  for (int i = 0; i < 12; ++i) {
    for (int j = t; j < 836; j += 128) {
      int p = base + j;
      s_in[j] = (p >= 0 && p < 9000) ? src[(size_t)(b*12+i)*9000 + p] : 0.f;
    }
    for (int j = t; j < 8*201; j += 128) {
      int o = j / 201, k = j % 201;
      s_w[j] = w[(size_t)(o*12 + i)*201 + k];
    }
    __syncthreads();
    if (l0 + t < 1800) {
      for (int k = 0; k < 201; ++k) {
        float v = s_in[5*t + k];
        #pragma unroll
        for (int o = 0; o < 8; ++o) acc[o] = fmaf(v, s_w[o*201 + k], acc[o]);
      }
    }
    __syncthreads();
  }
  int l = l0 + t;
  if (l < 1800) {
    #pragma unroll
    for (int o = 0; o < 8; ++o)
      out[(size_t)(b*8+o)*1800 + l] = acc[o] + bias[o];
  }
}

// ================= GroupNorm(1) stats =================
__global__ __launch_bounds__(256) void gn_stats_kernel(const float* __restrict__ x,
                                                       float* __restrict__ stats, int n)
{
  const int b = blockIdx.x;
  const float* xb = x + (size_t)b * n;
  float s = 0.f, q = 0.f;
  for (int i = threadIdx.x; i < n; i += 256) { float v = xb[i]; s += v; q += v*v; }
  __shared__ float sh1[256], sh2[256];
  sh1[threadIdx.x] = s; sh2[threadIdx.x] = q;
  __syncthreads();
  for (int st = 128; st > 0; st >>= 1) {
    if (threadIdx.x < st) { sh1[threadIdx.x] += sh1[threadIdx.x+st]; sh2[threadIdx.x] += sh2[threadIdx.x+st]; }
    __syncthreads();
  }
  if (threadIdx.x == 0) {
    float m = sh1[0] / n;
    float v = sh2[0] / n - m*m;
    stats[2*b]   = m;
    stats[2*b+1] = rsqrtf(v + 1e-5f);
  }
}

// ============ im2col conv2 + GN1 + GELU -> bf16 hi/lo ============
__global__ void im2col2_kernel(const float* __restrict__ c1,
    __nv_bfloat16* __restrict__ colh, __nv_bfloat16* __restrict__ coll,
    const float* __restrict__ stats, const float* __restrict__ g, const float* __restrict__ be)
{
  int idx = blockIdx.x*blockDim.x + threadIdx.x;
  if (idx >= 11520*808) return;
  int row = idx / 808, c = idx % 808;
  int i = c / 101, kk = c % 101;
  int b = row / 180, l = row % 180;
  int p = 10*l + kk - 50;
  float v = 0.f;
  if (p >= 0 && p < 1800) {
    float m = stats[2*b], r = stats[2*b+1];
    v = gelu_f((c1[(size_t)(b*8+i)*1800 + p] - m)*r*g[i] + be[i]);
  }
  __nv_bfloat16 h,l2; split_bf(v,h,l2);
  colh[idx]=h; coll[idx]=l2;
}

// ============ im2col conv3 + GN2 + GELU -> bf16 hi/lo ============
__global__ void im2col3_kernel(const float* __restrict__ c2g,
    __nv_bfloat16* __restrict__ colh, __nv_bfloat16* __restrict__ coll,
    const float* __restrict__ stats, const float* __restrict__ g, const float* __restrict__ be)
{
  int idx = blockIdx.x*blockDim.x + threadIdx.x;
  if (idx >= 1152*4080) return;
  int row = idx / 4080, c = idx % 4080;
  int i = c / 51, k = c % 51;
  int b = row / 18, l = row % 18;
  int p = 10*l + k - 25;
  float v = 0.f;
  if (p >= 0 && p < 180) {
    float m = stats[2*b], r = stats[2*b+1];
    v = gelu_f((c2g[(size_t)(b*180+p)*80 + i] - m)*r*g[i] + be[i]);
  }
  __nv_bfloat16 h,l2; split_bf(v,h,l2);
  colh[idx]=h; coll[idx]=l2;
}

// GN3 + GELU + PE -> x fp32 and bf16 hi/lo
__global__ void gn3_pe_kernel(const float* __restrict__ x, float* __restrict__ y,
    __nv_bfloat16* __restrict__ yh, __nv_bfloat16* __restrict__ yl,
    const float* __restrict__ stats, const float* __restrict__ g, const float* __restrict__ be)
{
  int idx = blockIdx.x*blockDim.x + threadIdx.x;
  if (idx >= 1152*800) return;
  int row = idx / 800, d = idx % 800;
  int b = row / 18, s = row % 18;
  float m = stats[2*b], r = stats[2*b+1];
  float v = gelu_f((x[idx]-m)*r*g[d] + be[d]);
  int de = d & ~1;
  float freq = expf((float)de * (-9.210340371976184f/800.f));
  float ang = (float)s * freq;
  v += (d & 1) ? cosf(ang) : sinf(ang);
  y[idx] = v;
  __nv_bfloat16 h,l; split_bf(v,h,l);
  yh[idx]=h; yl[idx]=l;
}

// ================= attention -> bf16 hi/lo out =================
__global__ __launch_bounds__(128) void attn_kernel(const float* __restrict__ qkv,
    __nv_bfloat16* __restrict__ outh, __nv_bfloat16* __restrict__ outl)
{
  const int b = blockIdx.x, h = blockIdx.y;
  const int tid = threadIdx.x;
  __shared__ float sq[1800], sk[1800], sv[1800], sc[324];
  for (int idx = tid; idx < 1800; idx += 128) {
    int s = idx/100, d = idx%100;
    size_t base = (size_t)(b*18+s)*2400 + h*100 + d;
    sq[idx] = qkv[base];
    sk[idx] = qkv[base + 800];
    sv[idx] = qkv[base + 1600];
  }
  __syncthreads();
  for (int p = tid; p < 324; p += 128) {
    int i = p/18, j = p%18;
    float dot = 0.f;
    #pragma unroll 4
    for (int d = 0; d < 100; ++d) dot = fmaf(sq[i*100+d], sk[j*100+d], dot);
    int di = i - j; if (di < 0) di = -di;
    float bias = (di > 2 && i != 0 && j != 0) ? -1e30f : 0.f;
    sc[p] = dot * 0.1f + bias;
  }
  __syncthreads();
  if (tid < 18) {
    float mx = -1e30f;
    for (int j = 0; j < 18; ++j) mx = fmaxf(mx, sc[tid*18+j]);
    float sum = 0.f;
    for (int j = 0; j < 18; ++j) { float e = expf(sc[tid*18+j]-mx); sc[tid*18+j] = e; sum += e; }
    float inv = 1.f/sum;
    for (int j = 0; j < 18; ++j) sc[tid*18+j] *= inv;
  }
  __syncthreads();
  for (int idx = tid; idx < 1800; idx += 128) {
    int i = idx/100, d = idx%100;
    float o = 0.f;
    #pragma unroll
    for (int j = 0; j < 18; ++j) o = fmaf(sc[i*18+j], sv[j*100+d], o);
    size_t oi = (size_t)(b*18+i)*800 + h*100 + d;
    __nv_bfloat16 hh,ll; split_bf(o,hh,ll);
    outh[oi]=hh; outl[oi]=ll;
  }
}

// ================= residual add + LayerNorm -> x fp32 + bf16 hi/lo =================
__global__ __launch_bounds__(256) void add_ln_kernel(float* __restrict__ x,
    __nv_bfloat16* __restrict__ xh, __nv_bfloat16* __restrict__ xl,
    const float* __restrict__ a, const float* __restrict__ g, const float* __restrict__ be)
{
  const int row = blockIdx.x;
  const int tid = threadIdx.x;
  __shared__ float t[800];
  __shared__ float sh1[256], sh2[256];
  float s = 0.f, q = 0.f;
  for (int d = tid; d < 800; d += 256) {
    float v = x[(size_t)row*800 + d] + a[(size_t)row*800 + d];
    t[d] = v; s += v; q += v*v;
  }
  sh1[tid] = s; sh2[tid] = q;
  __syncthreads();
  for (int st = 128; st > 0; st >>= 1) {
    if (tid < st) { sh1[tid] += sh1[tid+st]; sh2[tid] += sh2[tid+st]; }
    __syncthreads();
  }
  float m = sh1[0] / 800.f;
  float r = rsqrtf(sh2[0] / 800.f - m*m + 1e-5f);
  for (int d = tid; d < 800; d += 256) {
    float v = (t[d]-m)*r*g[d] + be[d];
    x[(size_t)row*800 + d] = v;
    __nv_bfloat16 h,l; split_bf(v,h,l);
    xh[(size_t)row*800 + d]=h; xl[(size_t)row*800 + d]=l;
  }
}

// ================= host =================
static float* symf(const void* s){ void* p; cudaGetSymbolAddress(&p, s); return (float*)p; }
static __nv_bfloat16* symb(const void* s){ void* p; cudaGetSymbolAddress(&p, s); return (__nv_bfloat16*)p; }

extern "C" void kernel_launch(void* const* d_in, const int* in_sizes, int n_in,
                              void* d_out, int out_size)
{
  const float* src        = (const float*)d_in[0];
  const float* cw1        = (const float*)d_in[1];
  const float* cb1        = (const float*)d_in[2];
  const float* gn1_g      = (const float*)d_in[3];
  const float* gn1_b      = (const float*)d_in[4];
  const float* cw2        = (const float*)d_in[5];
  const float* cb2        = (const float*)d_in[6];
  const float* gn2_g      = (const float*)d_in[7];
  const float* gn2_b      = (const float*)d_in[8];
  const float* cw3        = (const float*)d_in[9];
  const float* cb3        = (const float*)d_in[10];
  const float* gn3_g      = (const float*)d_in[11];
  const float* gn3_b      = (const float*)d_in[12];
  const float* in_proj_w  = (const float*)d_in[13];
  const float* in_proj_b  = (const float*)d_in[14];
  const float* attn_out_w = (const float*)d_in[15];
  const float* attn_out_b = (const float*)d_in[16];
  const float* lin1_w     = (const float*)d_in[17];
  const float* lin1_b     = (const float*)d_in[18];
  const float* lin2_w     = (const float*)d_in[19];
  const float* lin2_b     = (const float*)d_in[20];
  const float* ln1_g      = (const float*)d_in[21];
  const float* ln1_b      = (const float*)d_in[22];
  const float* ln2_g      = (const float*)d_in[23];
  const float* ln2_b      = (const float*)d_in[24];
  const float* out_w      = (const float*)d_in[25];
  const float* out_b      = (const float*)d_in[26];

  float* c1   = symf(g_c1);
  float* c2g  = symf(g_c2g);
  float* c3   = symf(g_c3);
  float* x    = symf(g_x);
  float* qkv  = symf(g_qkv);
  float* t1   = symf(g_t1);
  float* st   = symf(g_stats);
  __nv_bfloat16 *col2h=symb(g_col2h), *col2l=symb(g_col2l);
  __nv_bfloat16 *col3h=symb(g_col3h), *col3l=symb(g_col3l);
  __nv_bfloat16 *xh=symb(g_xh), *xl=symb(g_xl);
  __nv_bfloat16 *atth=symb(g_atth), *attl=symb(g_attl);
  __nv_bfloat16 *hh=symb(g_hh), *hl=symb(g_hl);
  __nv_bfloat16 *w2h=symb(g_w2h), *w2l=symb(g_w2l);
  __nv_bfloat16 *w3h=symb(g_w3h), *w3l=symb(g_w3l);
  __nv_bfloat16 *wiph=symb(g_wiph), *wipl=symb(g_wipl);
  __nv_bfloat16 *waoh=symb(g_waoh), *waol=symb(g_waol);
  __nv_bfloat16 *wl1h=symb(g_wl1h), *wl1l=symb(g_wl1l);
  __nv_bfloat16 *wl2h=symb(g_wl2h), *wl2l=symb(g_wl2l);
  __nv_bfloat16 *wouth=symb(g_wouth), *woutl=symb(g_woutl);

  cudaFuncSetAttribute(gemm4<0,0>, cudaFuncAttributeMaxDynamicSharedMemorySize, GEMM4_SMEM);
  cudaFuncSetAttribute(gemm4<1,1>, cudaFuncAttributeMaxDynamicSharedMemorySize, GEMM4_SMEM);

  // ---- weight conversions ----
  wconv_kernel<<<CDIV(80*808/4,256),256>>>(cw2, w2h, w2l, 80*808/4);
  wconv_kernel<<<CDIV(800*4080/4,256),256>>>(cw3, w3h, w3l, 800*4080/4);
  wconv_kernel<<<CDIV(8*2400*800/4,256),256>>>(in_proj_w, wiph, wipl, 8*2400*800/4);
  wconv_kernel<<<CDIV(8*800*800/4,256),256>>>(attn_out_w, waoh, waol, 8*800*800/4);
  wconv_kernel<<<CDIV(8*3200*800/4,256),256>>>(lin1_w, wl1h, wl1l, 8*3200*800/4);
  wconv_kernel<<<CDIV(8*800*3200/4,256),256>>>(lin2_w, wl2h, wl2l, 8*800*3200/4);
  wconv_kernel<<<CDIV(800*800/4,256),256>>>(out_w, wouth, woutl, 800*800/4);

  // ---- patch embedding ----
  conv1_kernel<<<dim3(64,15),128>>>(src, cw1, cb1, c1);
  gn_stats_kernel<<<64,256>>>(c1, st, 8*1800);
  im2col2_kernel<<<CDIV(11520*808,256),256>>>(c1, col2h, col2l, st, gn1_g, gn1_b);
  gemm4<0,0><<<dim3(1,180),256,GEMM4_SMEM>>>(col2h, col2l, w2h, w2l, cb2, c2g,
                                             nullptr, nullptr, 11520, 80, 808);
  gn_stats_kernel<<<64,256>>>(c2g, st, 180*80);
  im2col3_kernel<<<CDIV(1152*4080,256),256>>>(c2g, col3h, col3l, st, gn2_g, gn2_b);
  gemm4<0,0><<<dim3(7,18),256,GEMM4_SMEM>>>(col3h, col3l, w3h, w3l, cb3, c3,
                                            nullptr, nullptr, 1152, 800, 4080);
  gn_stats_kernel<<<64,256>>>(c3, st, 18*800);
  gn3_pe_kernel<<<CDIV(1152*800,256),256>>>(c3, x, xh, xl, st, gn3_g, gn3_b);

  // ---- transformer layers ----
  for (int i = 0; i < 8; ++i) {
    gemm4<0,0><<<dim3(19,18),256,GEMM4_SMEM>>>(xh, xl,
        wiph + (size_t)i*2400*800, wipl + (size_t)i*2400*800,
        in_proj_b + (size_t)i*2400, qkv, nullptr, nullptr, 1152, 2400, 800);
    attn_kernel<<<dim3(64,8),128>>>(qkv, atth, attl);
    gemm4<0,0><<<dim3(7,18),256,GEMM4_SMEM>>>(atth, attl,
        waoh + (size_t)i*800*800, waol + (size_t)i*800*800,
        attn_out_b + (size_t)i*800, t1, nullptr, nullptr, 1152, 800, 800);
    add_ln_kernel<<<1152,256>>>(x, xh, xl, t1, ln1_g + (size_t)i*800, ln1_b + (size_t)i*800);
    gemm4<1,1><<<dim3(25,18),256,GEMM4_SMEM>>>(xh, xl,
        wl1h + (size_t)i*3200*800, wl1l + (size_t)i*3200*800,
        lin1_b + (size_t)i*3200, nullptr, hh, hl, 1152, 3200, 800);
    gemm4<0,0><<<dim3(7,18),256,GEMM4_SMEM>>>(hh, hl,
        wl2h + (size_t)i*800*3200, wl2l + (size_t)i*800*3200,
        lin2_b + (size_t)i*800, t1, nullptr, nullptr, 1152, 800, 3200);
    add_ln_kernel<<<1152,256>>>(x, xh, xl, t1, ln2_g + (size_t)i*800, ln2_b + (size_t)i*800);
  }

  // ---- output projection ----
  gemm4<0,0><<<dim3(7,18),256,GEMM4_SMEM>>>(xh, xl, wouth, woutl, out_b,
                                            (float*)d_out, nullptr, nullptr, 1152, 800, 800);
}